// round 15
// baseline (speedup 1.0000x reference)
#include <cuda_runtime.h>
#include <cstdint>

namespace {

constexpr int Bn = 32768;
constexpr int Nn = 512;
constexpr int Fn = 8;
constexpr int On = 32;
constexpr int T  = 256;                    // 2 half-blocks x 128
constexpr int NBLK = 456;                  // 152 SMs x 3 resident blocks
constexpr int PAIRS = Bn / 2;              // 16384 row pairs

constexpr unsigned NB2 = 2u * Nn * Fn * 4; // 32768 B: two neighbor rows
constexpr unsigned MB2 = 2u * Nn * 4;      // 4096 B:  two mask rows

__device__ __forceinline__ uint32_t s2u(const void* p) {
    uint32_t a;
    asm("{ .reg .u64 t; cvta.to.shared.u64 t, %1; cvt.u32.u64 %0, t; }"
        : "=r"(a) : "l"(p));
    return a;
}

__device__ __forceinline__ void wait_parity(uint32_t mb, uint32_t ph) {
    uint32_t done;
    asm volatile(
        "{\n\t.reg .pred p;\n\t"
        "mbarrier.try_wait.parity.acquire.cta.shared::cta.b64 p, [%1], %2;\n\t"
        "selp.b32 %0, 1, 0, p;\n\t}"
        : "=r"(done) : "r"(mb), "r"(ph) : "memory");
    if (!done) {
        asm volatile(
            "{\n\t.reg .pred P1;\n\t"
            "W_%=:\n\t"
            "mbarrier.try_wait.parity.acquire.cta.shared::cta.b64 P1, [%0], %1, 0x989680;\n\t"
            "@P1 bra.uni D_%=;\n\t"
            "bra.uni W_%=;\n\t"
            "D_%=:\n\t}"
            :: "r"(mb), "r"(ph) : "memory");
    }
}

__device__ __forceinline__ void half_bar(int h) {
    asm volatile("bar.sync %0, 128;" :: "r"(h + 1) : "memory");
}

__global__ __launch_bounds__(T, 3)
void gat_kernel(const float* __restrict__ ego,          // [B, F]
                const float* __restrict__ neigh,        // [B, N, F]
                const int*   __restrict__ mask,         // [B, N] int32
                const float* __restrict__ W_ego,        // [F, F]
                const float* __restrict__ b_ego,        // [F]
                const float* __restrict__ w_attn,       // [2F]
                const float* __restrict__ b_attn,       // [1]
                const float* __restrict__ W_out,        // [F, OUT]
                const float* __restrict__ b_out,        // [OUT]
                float* __restrict__ out)                // [B, OUT]
{
    __shared__ alignas(128) float s_n[2][2 * Nn * Fn];  // 2 stages x 32 KB
    __shared__ alignas(128) int   s_m[2][2 * Nn];       // 2 stages x 4 KB
    __shared__ alignas(8) uint64_t full_b[2];
    __shared__ alignas(8) uint64_t empty_b[2];
    __shared__ float s_sum[2][2][4];                    // [iter&1][half][warp]
    __shared__ float s_part[2][2][4][Fn];

    const int t    = threadIdx.x;
    const int h    = t >> 7;          // half-block id (row within pair)
    const int u    = t & 127;         // thread id within half
    const int wh   = (t >> 5) & 3;    // warp within half
    const int lane = t & 31;
    const int pl   = u & 1;           // pair-lane: feature half I own
    const int b0   = blockIdx.x;
    const int nit  = (PAIRS - b0 + NBLK - 1) / NBLK;

    if (t == 0) {
        asm volatile("mbarrier.init.shared.b64 [%0], 1;"   :: "r"(s2u(&full_b[0]))  : "memory");
        asm volatile("mbarrier.init.shared.b64 [%0], 1;"   :: "r"(s2u(&full_b[1]))  : "memory");
        asm volatile("mbarrier.init.shared.b64 [%0], %1;"  :: "r"(s2u(&empty_b[0])), "r"(T) : "memory");
        asm volatile("mbarrier.init.shared.b64 [%0], %1;"  :: "r"(s2u(&empty_b[1])), "r"(T) : "memory");
    }
    __syncthreads();

    auto issue = [&](int i) {
        const size_t p = (size_t)b0 + (size_t)i * NBLK;   // pair index
        const int s = i & 1;
        const uint32_t mb = s2u(&full_b[s]);
        asm volatile("mbarrier.arrive.expect_tx.shared.b64 _, [%0], %1;"
                     :: "r"(mb), "r"(NB2 + MB2) : "memory");
        asm volatile("cp.async.bulk.shared::cta.global.mbarrier::complete_tx::bytes "
                     "[%0], [%1], %2, [%3];"
                     :: "r"(s2u(s_n[s])), "l"(neigh + p * (2 * Nn * Fn)),
                        "r"(NB2), "r"(mb) : "memory");
        asm volatile("cp.async.bulk.shared::cta.global.mbarrier::complete_tx::bytes "
                     "[%0], [%1], %2, [%3];"
                     :: "r"(s2u(s_m[s])), "l"(mask + p * (2 * Nn)),
                        "r"(MB2), "r"(mb) : "memory");
    };

    if (t == 32) {
        if (nit > 0) issue(0);
        if (nit > 1) issue(1);
    }

    // Feature-half weights (constant per thread).
    const float wa = w_attn[Fn + pl * 4 + 0];
    const float wb = w_attn[Fn + pl * 4 + 1];
    const float wc = w_attn[Fn + pl * 4 + 2];
    const float wd = w_attn[Fn + pl * 4 + 3];

    for (int i = 0; i < nit; i++) {
        const size_t pr = (size_t)b0 + (size_t)i * NBLK;
        const size_t b  = 2 * pr + h;          // my half's batch row
        const int s = i & 1;
        const uint32_t ph = (i >> 1) & 1;

        // ---- Ego scalar, computed per-warp (overlaps the TMA wait; operands
        //      L1/L2-resident). Lanes 0-7 each own one feature term.
        float tb;
        {
            float p = 0.f;
            if (lane < Fn) {
                p = b_ego[lane];
#pragma unroll
                for (int k = 0; k < Fn; k++)
                    p += ego[b * Fn + k] * W_ego[k * Fn + lane];
                p *= w_attn[lane];
            }
            p += __shfl_xor_sync(0xffffffffu, p, 4);
            p += __shfl_xor_sync(0xffffffffu, p, 2);
            p += __shfl_xor_sync(0xffffffffu, p, 1);
            tb = __shfl_sync(0xffffffffu, p, 0) + b_attn[0];
        }

        wait_parity(s2u(&full_b[s]), ph);

        // ---- Single smem pass into registers (16B lane stride: conflict-free).
        const float4* sn4 = reinterpret_cast<const float4*>(s_n[s]) + h * (Nn * Fn / 4);
        const int*    sm  = s_m[s] + h * Nn;
        float4 v[8];
        int mk[8];
#pragma unroll
        for (int j = 0; j < 8; j++) {
            v[j]  = sn4[u + j * 128];
            mk[j] = sm[(u >> 1) + j * 64];
        }
        // Stage drained for THIS thread: non-blocking release-arrive. Warps
        // proceed straight into compute; only the producer waits for all 256.
        asm volatile("mbarrier.arrive.release.cta.shared::cta.b64 _, [%0];"
                     :: "r"(s2u(&empty_b[s])) : "memory");
        if (t == 32 && i + 2 < nit) {
            wait_parity(s2u(&empty_b[s]), ph);   // all readers done
            issue(i + 2);
        }

        // ---- Fused score -> exp -> sum -> aggregation (no max pass: scores
        //      O(1) bounded; softmax shift-invariant).
        float sum = 0.f;
        float a0 = 0.f, a1 = 0.f, a2 = 0.f, a3 = 0.f;
#pragma unroll
        for (int j = 0; j < 8; j++) {
            float p = v[j].x * wa + v[j].y * wb + v[j].z * wc + v[j].w * wd;
            p += __shfl_xor_sync(0xffffffffu, p, 1);       // combine row halves
            const float e = mk[j] ? __expf(tb + p) : 0.f;
            if (pl == 0) sum += e;                          // count row once
            a0 += e * v[j].x; a1 += e * v[j].y;
            a2 += e * v[j].z; a3 += e * v[j].w;
        }
#pragma unroll
        for (int o = 16; o; o >>= 1)
            sum += __shfl_xor_sync(0xffffffffu, sum, o);
        if (lane == 0) s_sum[s][h][wh] = sum;

        // Parity-preserving butterfly: even lanes -> feats 0-3, odd -> 4-7.
#pragma unroll
        for (int o = 16; o >= 2; o >>= 1) {
            a0 += __shfl_xor_sync(0xffffffffu, a0, o);
            a1 += __shfl_xor_sync(0xffffffffu, a1, o);
            a2 += __shfl_xor_sync(0xffffffffu, a2, o);
            a3 += __shfl_xor_sync(0xffffffffu, a3, o);
        }
        if (lane < 2) {
            s_part[s][h][wh][pl * 4 + 0] = a0;
            s_part[s][h][wh][pl * 4 + 1] = a1;
            s_part[s][h][wh][pl * 4 + 2] = a2;
            s_part[s][h][wh][pl * 4 + 3] = a3;
        }
        half_bar(h);                      // row-local 4-warp reduction sync

        // ---- Epilogue by 32 threads of this half. All-masked: tot==0 -> b_out.
        if (u < On) {
            const float tot = s_sum[s][h][0] + s_sum[s][h][1] +
                              s_sum[s][h][2] + s_sum[s][h][3];
            const float rinv = (tot > 0.f) ? (1.f / tot) : 0.f;
            float o2 = b_out[u];
#pragma unroll
            for (int f = 0; f < Fn; f++) {
                const float ag = (s_part[s][h][0][f] + s_part[s][h][1][f] +
                                  s_part[s][h][2][f] + s_part[s][h][3][f]) * rinv;
                o2 += ag * W_out[f * On + u];
            }
            out[b * On + u] = o2;
        }
        // s_sum/s_part: i vs i+1 separated by the [s] double buffer; i vs i+2
        // same-parity reuse ordered by every warp's passage through
        // half_bar(i+1) (all half-mates have finished epilogue(i) by then).
    }
}

} // namespace

extern "C" void kernel_launch(void* const* d_in, const int* in_sizes, int n_in,
                              void* d_out, int out_size)
{
    const float* ego    = (const float*)d_in[0];
    const float* neigh  = (const float*)d_in[1];
    const int*   mask   = (const int*)d_in[2];
    const float* W_ego  = (const float*)d_in[3];
    const float* b_ego  = (const float*)d_in[4];
    const float* w_attn = (const float*)d_in[5];
    const float* b_attn = (const float*)d_in[6];
    const float* W_out  = (const float*)d_in[7];
    const float* b_out  = (const float*)d_in[8];
    float*       out    = (float*)d_out;

    gat_kernel<<<NBLK, T>>>(ego, neigh, mask, W_ego, b_ego, w_attn, b_attn,
                            W_out, b_out, out);
}

// round 16
// speedup vs baseline: 1.1262x; 1.1262x over previous
#include <cuda_runtime.h>
#include <cstdint>

namespace {

constexpr int Bn = 32768;
constexpr int Nn = 512;
constexpr int Fn = 8;
constexpr int On = 32;
constexpr int T  = 256;                    // 2 half-blocks x 128
constexpr int NBLK = 456;                  // 152 SMs x 3 resident blocks
constexpr int PAIRS = Bn / 2;              // 16384 row pairs
constexpr int NWARP = T / 32;              // 8 warps -> 8 empty arrivals

constexpr unsigned NB2 = 2u * Nn * Fn * 4; // 32768 B: two neighbor rows
constexpr unsigned MB2 = 2u * Nn * 4;      // 4096 B:  two mask rows

__device__ __forceinline__ uint32_t s2u(const void* p) {
    uint32_t a;
    asm("{ .reg .u64 t; cvta.to.shared.u64 t, %1; cvt.u32.u64 %0, t; }"
        : "=r"(a) : "l"(p));
    return a;
}

__device__ __forceinline__ void wait_parity(uint32_t mb, uint32_t ph) {
    uint32_t done;
    asm volatile(
        "{\n\t.reg .pred p;\n\t"
        "mbarrier.try_wait.parity.acquire.cta.shared::cta.b64 p, [%1], %2;\n\t"
        "selp.b32 %0, 1, 0, p;\n\t}"
        : "=r"(done) : "r"(mb), "r"(ph) : "memory");
    if (!done) {
        asm volatile(
            "{\n\t.reg .pred P1;\n\t"
            "W_%=:\n\t"
            "mbarrier.try_wait.parity.acquire.cta.shared::cta.b64 P1, [%0], %1, 0x989680;\n\t"
            "@P1 bra.uni D_%=;\n\t"
            "bra.uni W_%=;\n\t"
            "D_%=:\n\t}"
            :: "r"(mb), "r"(ph) : "memory");
    }
}

__device__ __forceinline__ void half_bar(int h) {
    asm volatile("bar.sync %0, 128;" :: "r"(h + 1) : "memory");
}

__global__ __launch_bounds__(T, 3)
void gat_kernel(const float* __restrict__ ego,          // [B, F]
                const float* __restrict__ neigh,        // [B, N, F]
                const int*   __restrict__ mask,         // [B, N] int32
                const float* __restrict__ W_ego,        // [F, F]
                const float* __restrict__ b_ego,        // [F]
                const float* __restrict__ w_attn,       // [2F]
                const float* __restrict__ b_attn,       // [1]
                const float* __restrict__ W_out,        // [F, OUT]
                const float* __restrict__ b_out,        // [OUT]
                float* __restrict__ out)                // [B, OUT]
{
    __shared__ alignas(128) float s_n[2][2 * Nn * Fn];  // 2 stages x 32 KB
    __shared__ alignas(128) int   s_m[2][2 * Nn];       // 2 stages x 4 KB
    __shared__ alignas(8) uint64_t full_b[2];
    __shared__ alignas(8) uint64_t empty_b[2];
    __shared__ float s_sum[2][2][4];                    // [iter&1][half][warp]
    __shared__ float s_part[2][2][4][Fn];

    const int t    = threadIdx.x;
    const int h    = t >> 7;          // half-block id (row within pair)
    const int u    = t & 127;         // thread id within half
    const int wh   = (t >> 5) & 3;    // warp within half
    const int lane = t & 31;
    const int pl   = u & 1;           // pair-lane: feature half I own
    const int b0   = blockIdx.x;
    const int nit  = (PAIRS - b0 + NBLK - 1) / NBLK;

    if (t == 0) {
        asm volatile("mbarrier.init.shared.b64 [%0], 1;"  :: "r"(s2u(&full_b[0]))  : "memory");
        asm volatile("mbarrier.init.shared.b64 [%0], 1;"  :: "r"(s2u(&full_b[1]))  : "memory");
        asm volatile("mbarrier.init.shared.b64 [%0], %1;" :: "r"(s2u(&empty_b[0])), "r"(NWARP) : "memory");
        asm volatile("mbarrier.init.shared.b64 [%0], %1;" :: "r"(s2u(&empty_b[1])), "r"(NWARP) : "memory");
    }
    __syncthreads();

    auto issue = [&](int i) {
        const size_t p = (size_t)b0 + (size_t)i * NBLK;   // pair index
        const int s = i & 1;
        const uint32_t mb = s2u(&full_b[s]);
        asm volatile("mbarrier.arrive.expect_tx.shared.b64 _, [%0], %1;"
                     :: "r"(mb), "r"(NB2 + MB2) : "memory");
        asm volatile("cp.async.bulk.shared::cta.global.mbarrier::complete_tx::bytes "
                     "[%0], [%1], %2, [%3];"
                     :: "r"(s2u(s_n[s])), "l"(neigh + p * (2 * Nn * Fn)),
                        "r"(NB2), "r"(mb) : "memory");
        asm volatile("cp.async.bulk.shared::cta.global.mbarrier::complete_tx::bytes "
                     "[%0], [%1], %2, [%3];"
                     :: "r"(s2u(s_m[s])), "l"(mask + p * (2 * Nn)),
                        "r"(MB2), "r"(mb) : "memory");
    };

    if (t == 32) {
        if (nit > 0) issue(0);
        if (nit > 1) issue(1);
    }

    // Feature-half weights (constant per thread).
    const float wa = w_attn[Fn + pl * 4 + 0];
    const float wb = w_attn[Fn + pl * 4 + 1];
    const float wc = w_attn[Fn + pl * 4 + 2];
    const float wd = w_attn[Fn + pl * 4 + 3];

    for (int i = 0; i < nit; i++) {
        const size_t pr = (size_t)b0 + (size_t)i * NBLK;
        const size_t b  = 2 * pr + h;          // my half's batch row
        const int s = i & 1;
        const uint32_t ph = (i >> 1) & 1;

        // ---- Ego scalar, per-warp (overlaps TMA wait; operands L1/L2-resident).
        float tb;
        {
            float p = 0.f;
            if (lane < Fn) {
                p = b_ego[lane];
#pragma unroll
                for (int k = 0; k < Fn; k++)
                    p += ego[b * Fn + k] * W_ego[k * Fn + lane];
                p *= w_attn[lane];
            }
            p += __shfl_xor_sync(0xffffffffu, p, 4);
            p += __shfl_xor_sync(0xffffffffu, p, 2);
            p += __shfl_xor_sync(0xffffffffu, p, 1);
            tb = __shfl_sync(0xffffffffu, p, 0) + b_attn[0];
        }

        wait_parity(s2u(&full_b[s]), ph);

        // ---- Single smem pass into registers (16B lane stride: conflict-free).
        const float4* sn4 = reinterpret_cast<const float4*>(s_n[s]) + h * (Nn * Fn / 4);
        const int*    sm  = s_m[s] + h * Nn;
        float4 v[8];
        int mk[8];
#pragma unroll
        for (int j = 0; j < 8; j++) {
            v[j]  = sn4[u + j * 128];
            mk[j] = sm[(u >> 1) + j * 64];
        }
        // Warp-elected stage release: 8 arrivals total, not 256. Non-blocking;
        // compute warps flow straight on. Only the producer drains it.
        __syncwarp();
        if (lane == 0)
            asm volatile("mbarrier.arrive.release.cta.shared::cta.b64 _, [%0];"
                         :: "r"(s2u(&empty_b[s])) : "memory");
        if (t == 32 && i + 2 < nit) {
            wait_parity(s2u(&empty_b[s]), ph);   // all 8 warps drained stage s
            issue(i + 2);
        }

        // ---- Fused score -> exp -> sum -> aggregation (no max pass: scores
        //      O(1) bounded; softmax shift-invariant).
        float sum = 0.f;
        float a0 = 0.f, a1 = 0.f, a2 = 0.f, a3 = 0.f;
#pragma unroll
        for (int j = 0; j < 8; j++) {
            float p = v[j].x * wa + v[j].y * wb + v[j].z * wc + v[j].w * wd;
            p += __shfl_xor_sync(0xffffffffu, p, 1);       // combine row halves
            const float e = mk[j] ? __expf(tb + p) : 0.f;
            if (pl == 0) sum += e;                          // count row once
            a0 += e * v[j].x; a1 += e * v[j].y;
            a2 += e * v[j].z; a3 += e * v[j].w;
        }
#pragma unroll
        for (int o = 16; o; o >>= 1)
            sum += __shfl_xor_sync(0xffffffffu, sum, o);
        if (lane == 0) s_sum[s][h][wh] = sum;

        // Parity-preserving butterfly: even lanes -> feats 0-3, odd -> 4-7.
#pragma unroll
        for (int o = 16; o >= 2; o >>= 1) {
            a0 += __shfl_xor_sync(0xffffffffu, a0, o);
            a1 += __shfl_xor_sync(0xffffffffu, a1, o);
            a2 += __shfl_xor_sync(0xffffffffu, a2, o);
            a3 += __shfl_xor_sync(0xffffffffu, a3, o);
        }
        if (lane < 2) {
            s_part[s][h][wh][pl * 4 + 0] = a0;
            s_part[s][h][wh][pl * 4 + 1] = a1;
            s_part[s][h][wh][pl * 4 + 2] = a2;
            s_part[s][h][wh][pl * 4 + 3] = a3;
        }
        half_bar(h);                      // row-local 4-warp reduction sync

        // ---- Epilogue by 32 threads of this half. All-masked: tot==0 -> b_out.
        if (u < On) {
            const float tot = s_sum[s][h][0] + s_sum[s][h][1] +
                              s_sum[s][h][2] + s_sum[s][h][3];
            const float rinv = (tot > 0.f) ? (1.f / tot) : 0.f;
            float o2 = b_out[u];
#pragma unroll
            for (int f = 0; f < Fn; f++) {
                const float ag = (s_part[s][h][0][f] + s_part[s][h][1][f] +
                                  s_part[s][h][2][f] + s_part[s][h][3][f]) * rinv;
                o2 += ag * W_out[f * On + u];
            }
            out[b * On + u] = o2;
        }
        // s_sum/s_part: i vs i+1 separated by [s]; i vs i+2 ordered by each
        // thread's program order epilogue(i) -> half_bar(i+1) -> write(i+2).
    }
}

} // namespace

extern "C" void kernel_launch(void* const* d_in, const int* in_sizes, int n_in,
                              void* d_out, int out_size)
{
    const float* ego    = (const float*)d_in[0];
    const float* neigh  = (const float*)d_in[1];
    const int*   mask   = (const int*)d_in[2];
    const float* W_ego  = (const float*)d_in[3];
    const float* b_ego  = (const float*)d_in[4];
    const float* w_attn = (const float*)d_in[5];
    const float* b_attn = (const float*)d_in[6];
    const float* W_out  = (const float*)d_in[7];
    const float* b_out  = (const float*)d_in[8];
    float*       out    = (float*)d_out;

    gat_kernel<<<NBLK, T>>>(ego, neigh, mask, W_ego, b_ego, w_attn, b_attn,
                            W_out, b_out, out);
}

// round 17
// speedup vs baseline: 1.6416x; 1.4577x over previous
#include <cuda_runtime.h>
#include <cstdint>

namespace {

constexpr int Bn = 32768;
constexpr int Nn = 512;
constexpr int Fn = 8;
constexpr int On = 32;
constexpr int T  = 256;                    // 2 half-blocks x 128
constexpr int NBLK = 456;                  // 152 SMs x 3 resident blocks
constexpr int PAIRS = Bn / 2;              // 16384 row pairs

constexpr unsigned NB2 = 2u * Nn * Fn * 4; // 32768 B: two neighbor rows
constexpr unsigned MB2 = 2u * Nn * 4;      // 4096 B:  two mask rows

__device__ __forceinline__ uint32_t s2u(const void* p) {
    uint32_t a;
    asm("{ .reg .u64 t; cvta.to.shared.u64 t, %1; cvt.u32.u64 %0, t; }"
        : "=r"(a) : "l"(p));
    return a;
}

__device__ __forceinline__ void wait_parity(uint32_t mb, uint32_t ph) {
    uint32_t done;
    asm volatile(
        "{\n\t.reg .pred p;\n\t"
        "mbarrier.try_wait.parity.acquire.cta.shared::cta.b64 p, [%1], %2;\n\t"
        "selp.b32 %0, 1, 0, p;\n\t}"
        : "=r"(done) : "r"(mb), "r"(ph) : "memory");
    if (!done) {
        asm volatile(
            "{\n\t.reg .pred P1;\n\t"
            "W_%=:\n\t"
            "mbarrier.try_wait.parity.acquire.cta.shared::cta.b64 P1, [%0], %1, 0x989680;\n\t"
            "@P1 bra.uni D_%=;\n\t"
            "bra.uni W_%=;\n\t"
            "D_%=:\n\t}"
            :: "r"(mb), "r"(ph) : "memory");
    }
}

__device__ __forceinline__ void half_bar(int h) {
    asm volatile("bar.sync %0, 128;" :: "r"(h + 1) : "memory");
}

__global__ __launch_bounds__(T, 3)
void gat_kernel(const float* __restrict__ ego,          // [B, F]
                const float* __restrict__ neigh,        // [B, N, F]
                const int*   __restrict__ mask,         // [B, N] int32
                const float* __restrict__ W_ego,        // [F, F]
                const float* __restrict__ b_ego,        // [F]
                const float* __restrict__ w_attn,       // [2F]
                const float* __restrict__ b_attn,       // [1]
                const float* __restrict__ W_out,        // [F, OUT]
                const float* __restrict__ b_out,        // [OUT]
                float* __restrict__ out)                // [B, OUT]
{
    __shared__ alignas(128) float s_n[2][2 * Nn * Fn];  // 2 stages x 32 KB
    __shared__ alignas(128) int   s_m[2][2 * Nn];       // 2 stages x 4 KB
    __shared__ alignas(8) uint64_t mbar[2];
    __shared__ float s_sum[2][2][4];                    // [iter&1][half][warp]
    __shared__ float s_part[2][2][4][Fn];

    const int t    = threadIdx.x;
    const int h    = t >> 7;          // half-block id (row within pair)
    const int u    = t & 127;         // thread id within half
    const int wh   = (t >> 5) & 3;    // warp within half
    const int lane = t & 31;
    const int pl   = u & 1;           // pair-lane: feature half I own
    const int b0   = blockIdx.x;
    const int nit  = (PAIRS - b0 + NBLK - 1) / NBLK;

    if (t == 0) {
        asm volatile("mbarrier.init.shared.b64 [%0], 1;" :: "r"(s2u(&mbar[0])) : "memory");
        asm volatile("mbarrier.init.shared.b64 [%0], 1;" :: "r"(s2u(&mbar[1])) : "memory");
    }
    __syncthreads();

    auto issue = [&](int i) {
        const size_t p = (size_t)b0 + (size_t)i * NBLK;   // pair index
        const int s = i & 1;
        const uint32_t mb = s2u(&mbar[s]);
        asm volatile("mbarrier.arrive.expect_tx.shared.b64 _, [%0], %1;"
                     :: "r"(mb), "r"(NB2 + MB2) : "memory");
        asm volatile("cp.async.bulk.shared::cta.global.mbarrier::complete_tx::bytes "
                     "[%0], [%1], %2, [%3];"
                     :: "r"(s2u(s_n[s])), "l"(neigh + p * (2 * Nn * Fn)),
                        "r"(NB2), "r"(mb) : "memory");
        asm volatile("cp.async.bulk.shared::cta.global.mbarrier::complete_tx::bytes "
                     "[%0], [%1], %2, [%3];"
                     :: "r"(s2u(s_m[s])), "l"(mask + p * (2 * Nn)),
                        "r"(MB2), "r"(mb) : "memory");
    };

    if (t == 0) {
        if (nit > 0) issue(0);
        if (nit > 1) issue(1);
    }

    // Feature-half weights (constant per thread).
    const float wa = w_attn[Fn + pl * 4 + 0];
    const float wb = w_attn[Fn + pl * 4 + 1];
    const float wc = w_attn[Fn + pl * 4 + 2];
    const float wd = w_attn[Fn + pl * 4 + 3];

    for (int i = 0; i < nit; i++) {
        const size_t pr = (size_t)b0 + (size_t)i * NBLK;
        const size_t b  = 2 * pr + h;          // my half's batch row
        const int s = i & 1;
        const uint32_t ph = (i >> 1) & 1;

        // ---- Ego scalar, per-warp (overlaps TMA wait; operands L1-resident;
        //      numerically identical to leader version — validated R15/R16).
        float tb;
        {
            float p = 0.f;
            if (lane < Fn) {
                p = b_ego[lane];
#pragma unroll
                for (int k = 0; k < Fn; k++)
                    p += ego[b * Fn + k] * W_ego[k * Fn + lane];
                p *= w_attn[lane];
            }
            p += __shfl_xor_sync(0xffffffffu, p, 4);
            p += __shfl_xor_sync(0xffffffffu, p, 2);
            p += __shfl_xor_sync(0xffffffffu, p, 1);
            tb = __shfl_sync(0xffffffffu, p, 0) + b_attn[0];
        }

        wait_parity(s2u(&mbar[s]), ph);

        // ---- Single smem pass into registers (16B lane stride: conflict-free).
        const float4* sn4 = reinterpret_cast<const float4*>(s_n[s]) + h * (Nn * Fn / 4);
        const int*    sm  = s_m[s] + h * Nn;
        float4 v[8];
        int mk[8];
#pragma unroll
        for (int j = 0; j < 8; j++) {
            v[j]  = sn4[u + j * 128];
            mk[j] = sm[(u >> 1) + j * 64];
        }
        __syncthreads();                  // stage drained by ALL: HW barrier,
        if (t == 0 && i + 2 < nit)        // then prefetch immediately
            issue(i + 2);

        // ---- Fused score -> exp -> sum -> aggregation (no max pass: scores
        //      O(1) bounded; softmax shift-invariant).
        float sum = 0.f;
        float a0 = 0.f, a1 = 0.f, a2 = 0.f, a3 = 0.f;
#pragma unroll
        for (int j = 0; j < 8; j++) {
            float p = v[j].x * wa + v[j].y * wb + v[j].z * wc + v[j].w * wd;
            p += __shfl_xor_sync(0xffffffffu, p, 1);       // combine row halves
            const float e = mk[j] ? __expf(tb + p) : 0.f;
            if (pl == 0) sum += e;                          // count row once
            a0 += e * v[j].x; a1 += e * v[j].y;
            a2 += e * v[j].z; a3 += e * v[j].w;
        }
#pragma unroll
        for (int o = 16; o; o >>= 1)
            sum += __shfl_xor_sync(0xffffffffu, sum, o);
        if (lane == 0) s_sum[s][h][wh] = sum;

        // Parity-preserving butterfly: even lanes -> feats 0-3, odd -> 4-7.
#pragma unroll
        for (int o = 16; o >= 2; o >>= 1) {
            a0 += __shfl_xor_sync(0xffffffffu, a0, o);
            a1 += __shfl_xor_sync(0xffffffffu, a1, o);
            a2 += __shfl_xor_sync(0xffffffffu, a2, o);
            a3 += __shfl_xor_sync(0xffffffffu, a3, o);
        }
        if (lane < 2) {
            s_part[s][h][wh][pl * 4 + 0] = a0;
            s_part[s][h][wh][pl * 4 + 1] = a1;
            s_part[s][h][wh][pl * 4 + 2] = a2;
            s_part[s][h][wh][pl * 4 + 3] = a3;
        }
        half_bar(h);                      // row-local 4-warp reduction sync

        // ---- Epilogue by 32 threads of this half. All-masked: tot==0 -> b_out.
        if (u < On) {
            const float tot = s_sum[s][h][0] + s_sum[s][h][1] +
                              s_sum[s][h][2] + s_sum[s][h][3];
            const float rinv = (tot > 0.f) ? (1.f / tot) : 0.f;
            float o2 = b_out[u];
#pragma unroll
            for (int f = 0; f < Fn; f++) {
                const float ag = (s_part[s][h][0][f] + s_part[s][h][1][f] +
                                  s_part[s][h][2][f] + s_part[s][h][3][f]) * rinv;
                o2 += ag * W_out[f * On + u];
            }
            out[b * On + u] = o2;
        }
        // s_sum/s_part: i vs i+1 separated by [s]; i vs i+2 ordered by the
        // next iteration's __syncthreads.
    }
}

} // namespace

extern "C" void kernel_launch(void* const* d_in, const int* in_sizes, int n_in,
                              void* d_out, int out_size)
{
    const float* ego    = (const float*)d_in[0];
    const float* neigh  = (const float*)d_in[1];
    const int*   mask   = (const int*)d_in[2];
    const float* W_ego  = (const float*)d_in[3];
    const float* b_ego  = (const float*)d_in[4];
    const float* w_attn = (const float*)d_in[5];
    const float* b_attn = (const float*)d_in[6];
    const float* W_out  = (const float*)d_in[7];
    const float* b_out  = (const float*)d_in[8];
    float*       out    = (float*)d_out;

    gat_kernel<<<NBLK, T>>>(ego, neigh, mask, W_ego, b_ego, w_attn, b_attn,
                            W_out, b_out, out);
}